// round 12
// baseline (speedup 1.0000x reference)
#include <cuda_runtime.h>
#include <cstdint>

#define NUM_GRAPHS 16384
#define EMB_DIM 128

// Precomputed segment boundaries (lower_bound of each graph id).
__device__ int g_offs_atoms[NUM_GRAPHS + 1];
__device__ int g_offs_frags[NUM_GRAPHS + 1];

__device__ __forceinline__ int idx_at(const void* __restrict__ b, int i, bool is64) {
    if (is64) return (int)(((const long long* __restrict__)b)[i]);
    return ((const int* __restrict__)b)[i];
}

// Ids sorted in [0,16384). As int32, position n-1 (odd) is an int64 high word
// => 0 under int64 layout; nonzero (largest id) under int32 layout.
__device__ __forceinline__ bool detect_is64(const void* __restrict__ b, int n) {
    return ((const int* __restrict__)b)[n - 1] == 0;
}

// Fused vectorized prologue, 16 elements per thread.
__global__ void build_offsets_fused(const void* __restrict__ a, int na, int* __restrict__ offsA,
                                    const void* __restrict__ f, int nf, int* __restrict__ offsF) {
    const int chunksA = (na + 15) >> 4;
    const int chunksF = (nf + 15) >> 4;
    const int total   = chunksA + chunksF;
    const int stride  = gridDim.x * blockDim.x;

    for (int c = blockIdx.x * blockDim.x + threadIdx.x; c < total; c += stride) {
        const bool isF = (c >= chunksA);
        const void* __restrict__ b = isF ? f : a;
        const int n = isF ? nf : na;
        int* __restrict__ offs = isF ? offsF : offsA;
        const int base = (isF ? (c - chunksA) : c) << 4;
        const bool is64 = detect_is64(b, n);

        int ids[16];
        if (base + 16 <= n) {
            if (is64) {
                const ulonglong2* p = (const ulonglong2*)((const long long*)b + base);
                ulonglong2 w0 = __ldcg(p),     w1 = __ldcg(p + 1), w2 = __ldcg(p + 2), w3 = __ldcg(p + 3);
                ulonglong2 w4 = __ldcg(p + 4), w5 = __ldcg(p + 5), w6 = __ldcg(p + 6), w7 = __ldcg(p + 7);
                ids[0]  = (int)w0.x; ids[1]  = (int)w0.y; ids[2]  = (int)w1.x; ids[3]  = (int)w1.y;
                ids[4]  = (int)w2.x; ids[5]  = (int)w2.y; ids[6]  = (int)w3.x; ids[7]  = (int)w3.y;
                ids[8]  = (int)w4.x; ids[9]  = (int)w4.y; ids[10] = (int)w5.x; ids[11] = (int)w5.y;
                ids[12] = (int)w6.x; ids[13] = (int)w6.y; ids[14] = (int)w7.x; ids[15] = (int)w7.y;
            } else {
                const int4* p = (const int4*)((const int*)b + base);
                int4 v0 = __ldcg(p), v1 = __ldcg(p + 1), v2 = __ldcg(p + 2), v3 = __ldcg(p + 3);
                ids[0]  = v0.x; ids[1]  = v0.y; ids[2]  = v0.z; ids[3]  = v0.w;
                ids[4]  = v1.x; ids[5]  = v1.y; ids[6]  = v1.z; ids[7]  = v1.w;
                ids[8]  = v2.x; ids[9]  = v2.y; ids[10] = v2.z; ids[11] = v2.w;
                ids[12] = v3.x; ids[13] = v3.y; ids[14] = v3.z; ids[15] = v3.w;
            }
            int prev = (base == 0) ? -1 : idx_at(b, base - 1, is64);
            #pragma unroll
            for (int j = 0; j < 16; j++) {
                const int cur = ids[j];
                if (cur != prev) {
                    for (int id = prev + 1; id <= cur; ++id) offs[id] = base + j;
                    prev = cur;
                }
            }
            if (base + 16 == n) {
                for (int id = ids[15] + 1; id <= NUM_GRAPHS; ++id) offs[id] = n;
            }
        } else {
            int prev = (base == 0) ? -1 : idx_at(b, base - 1, is64);
            for (int i = base; i < n; i++) {
                const int cur = idx_at(b, i, is64);
                for (int id = prev + 1; id <= cur; ++id) offs[id] = i;
                prev = cur;
                if (i == n - 1) {
                    for (int id = cur + 1; id <= NUM_GRAPHS; ++id) offs[id] = n;
                }
            }
        }
    }
}

__device__ __forceinline__ float4 f4_add(const float4& a, const float4& b) {
    return make_float4(a.x + b.x, a.y + b.y, a.z + b.z, a.w + b.w);
}

// Sum a warp-strided segment [start+warp, end) step 4 with a 3-tier unrolled
// loop: 8 independent LDG.128 in flight, then 4, then 1. Returns per-lane acc.
__device__ __forceinline__ float4 stream_sum(const float* __restrict__ x,
                                             int start, int end, int warp, int lane) {
    float4 acc0 = make_float4(0.f, 0.f, 0.f, 0.f);
    float4 acc1 = make_float4(0.f, 0.f, 0.f, 0.f);
    int r = start + warp;
    const float4* p = reinterpret_cast<const float4*>(x + (size_t)r * EMB_DIM) + lane;

    // Tier 1: 8 strided rows (consumes 32 segment rows).
    for (; r + 28 < end; r += 32, p += 1024) {
        float4 v0 = __ldcg(p);
        float4 v1 = __ldcg(p + 128);
        float4 v2 = __ldcg(p + 256);
        float4 v3 = __ldcg(p + 384);
        float4 v4 = __ldcg(p + 512);
        float4 v5 = __ldcg(p + 640);
        float4 v6 = __ldcg(p + 768);
        float4 v7 = __ldcg(p + 896);
        acc0 = f4_add(acc0, f4_add(f4_add(v0, v1), f4_add(v2, v3)));
        acc1 = f4_add(acc1, f4_add(f4_add(v4, v5), f4_add(v6, v7)));
    }
    // Tier 2: 4 strided rows.
    for (; r + 12 < end; r += 16, p += 512) {
        float4 v0 = __ldcg(p);
        float4 v1 = __ldcg(p + 128);
        float4 v2 = __ldcg(p + 256);
        float4 v3 = __ldcg(p + 384);
        acc0 = f4_add(acc0, f4_add(f4_add(v0, v1), f4_add(v2, v3)));
    }
    // Tier 3: single rows.
    for (; r < end; r += 4, p += 128) {
        acc0 = f4_add(acc0, __ldcg(p));
    }
    return f4_add(acc0, acc1);
}

// One-shot CTA-per-graph pooling: warps stride rows by 4, each lane one float4
// => full 512B row per warp-iteration (coalesced LDG.128, L1-bypass).
__global__ __launch_bounds__(128, 8)
void fragnet_pool_kernel(const float* __restrict__ x_atoms,
                         const float* __restrict__ x_frags,
                         float* __restrict__ out) {
    const int g    = blockIdx.x;
    const int warp = threadIdx.x >> 5;
    const int lane = threadIdx.x & 31;

    __shared__ int bounds[4];          // [a_start, a_end, f_start, f_end]
    __shared__ float4 shA[4][32];
    __shared__ float4 shF[4][32];

    if (threadIdx.x < 4) {
        const int* offs = (threadIdx.x >= 2) ? g_offs_frags : g_offs_atoms;
        bounds[threadIdx.x] = offs[g + (threadIdx.x & 1)];
    }
    __syncthreads();

    shA[warp][lane] = stream_sum(x_atoms, bounds[0], bounds[1], warp, lane);
    shF[warp][lane] = stream_sum(x_frags, bounds[2], bounds[3], warp, lane);
    __syncthreads();

    // Warp 0 reduces+writes the atoms half, warp 1 the frags half.
    if (warp < 2) {
        const float4 (*sh)[32] = (warp == 0) ? shA : shF;
        float4 s = f4_add(f4_add(sh[0][lane], sh[1][lane]),
                          f4_add(sh[2][lane], sh[3][lane]));
        reinterpret_cast<float4*>(out + (size_t)g * (2 * EMB_DIM) + warp * EMB_DIM)[lane] = s;
    }
}

extern "C" void kernel_launch(void* const* d_in, const int* in_sizes, int n_in,
                              void* d_out, int out_size) {
    const float* x_atoms    = (const float*)d_in[0];
    const float* x_frags    = (const float*)d_in[1];
    const void*  batch      = d_in[2];
    const void*  frag_batch = d_in[3];
    float* out = (float*)d_out;

    const int n_atoms = in_sizes[2];
    const int n_frags = in_sizes[3];

    int* offs_atoms = nullptr;
    int* offs_frags = nullptr;
    cudaGetSymbolAddress((void**)&offs_atoms, g_offs_atoms);
    cudaGetSymbolAddress((void**)&offs_frags, g_offs_frags);

    const int chunks = ((n_atoms + 15) >> 4) + ((n_frags + 15) >> 4);
    const int T = 256;
    build_offsets_fused<<<(chunks + T - 1) / T, T>>>(batch, n_atoms, offs_atoms,
                                                     frag_batch, n_frags, offs_frags);
    fragnet_pool_kernel<<<NUM_GRAPHS, 128>>>(x_atoms, x_frags, out);
}